// round 5
// baseline (speedup 1.0000x reference)
#include <cuda_runtime.h>
#include <cuda_bf16.h>
#include <cstdint>

// BNB 8-bit embedding dequant-on-gather — bulk-async row fetch (sm_103a).
// Identities: row base = q_idx + id*1024; scale = absmax[id>>2].
//
// Each CTA handles 8 tokens. One thread issues 8 cp.async.bulk copies
// (4 KB each, whole row) into SMEM against one mbarrier; after the barrier
// flips, 256 threads dequant from SMEM and emit 256-bit streaming stores.

#define TPC 8           // tokens per CTA
#define ROW_BYTES 4096

__device__ __forceinline__ uint32_t smem_u32(const void* p) {
    uint32_t a;
    asm("{ .reg .u64 t; cvta.to.shared.u64 t, %1; cvt.u32.u64 %0, t; }"
        : "=r"(a) : "l"(p));
    return a;
}

__device__ __forceinline__ void stg_cs_v8(float* p, const float o[8]) {
    asm volatile("st.global.cs.v8.f32 [%0], {%1,%2,%3,%4,%5,%6,%7,%8};"
                 :: "l"(p),
                    "f"(o[0]), "f"(o[1]), "f"(o[2]), "f"(o[3]),
                    "f"(o[4]), "f"(o[5]), "f"(o[6]), "f"(o[7])
                 : "memory");
}

__global__ __launch_bounds__(256)
void bnb8bit_embedding_kernel(const int* __restrict__ x,
                              const int* __restrict__ q_idx,
                              const float* __restrict__ absmax,
                              const float* __restrict__ code,
                              float* __restrict__ out,
                              int n_tokens) {
    __shared__ float s_code[256];
    __shared__ float s_scale[TPC];
    __shared__ int   s_ids[TPC];
    __shared__ __align__(16) unsigned long long s_mbar;
    __shared__ __align__(128) int s_rows[TPC][ROW_BYTES / 4];

    const int t = threadIdx.x;
    s_code[t] = code[t];

    const int base   = blockIdx.x * TPC;
    const int nvalid = min(TPC, n_tokens - base);

    if (t < TPC) {
        int tok = base + t;
        int id  = (t < nvalid) ? x[tok] : 0;
        s_ids[t]   = id;
        s_scale[t] = __ldg(absmax + (id >> 2));
    }

    const uint32_t mbar = smem_u32(&s_mbar);
    if (t == 0) {
        asm volatile("mbarrier.init.shared.b64 [%0], 1;" :: "r"(mbar) : "memory");
    }
    __syncthreads();   // ids visible + mbarrier initialized before use

    if (t == 0) {
        asm volatile("mbarrier.arrive.expect_tx.shared.b64 _, [%0], %1;"
                     :: "r"(mbar), "r"((uint32_t)(nvalid * ROW_BYTES)) : "memory");
        #pragma unroll
        for (int i = 0; i < TPC; i++) {
            if (i < nvalid) {
                uint32_t dst = smem_u32(&s_rows[i][0]);
                const int* src = q_idx + (size_t)s_ids[i] * 1024;
                asm volatile(
                    "cp.async.bulk.shared::cta.global.mbarrier::complete_tx::bytes "
                    "[%0], [%1], %2, [%3];"
                    :: "r"(dst), "l"(src), "r"((uint32_t)ROW_BYTES), "r"(mbar)
                    : "memory");
            }
        }
    }

    // Wait for all rows (phase 0, acquire).
    {
        uint32_t done;
        asm volatile(
            "{\n\t"
            ".reg .pred p;\n\t"
            "mbarrier.try_wait.parity.acquire.cta.shared::cta.b64 p, [%1], 0;\n\t"
            "selp.b32 %0, 1, 0, p;\n\t"
            "}" : "=r"(done) : "r"(mbar) : "memory");
        if (!done) {
            asm volatile(
                "{\n\t"
                ".reg .pred P1;\n\t"
                "WL_%=:\n\t"
                "mbarrier.try_wait.parity.acquire.cta.shared::cta.b64 P1, [%0], 0, 0x989680;\n\t"
                "@P1 bra.uni WD_%=;\n\t"
                "bra.uni WL_%=;\n\t"
                "WD_%=:\n\t"
                "}" :: "r"(mbar) : "memory");
        }
    }

    // Dequant + store: 4 passes, 256 threads x 32B each = 8 KB (2 rows) per pass.
    #pragma unroll
    for (int c = 0; c < 4; c++) {
        const int idx = c * 256 + t;          // 0..1023
        const int row = idx >> 7;             // 0..7
        const int seg = idx & 127;            // 32B segment in row
        if (row < nvalid) {
            const float sc = s_scale[row];
            const int4* sp = reinterpret_cast<const int4*>(&s_rows[row][seg * 8]);
            int4 a = sp[0];
            int4 b = sp[1];
            float o[8];
            o[0] = s_code[a.x] * sc;  o[1] = s_code[a.y] * sc;
            o[2] = s_code[a.z] * sc;  o[3] = s_code[a.w] * sc;
            o[4] = s_code[b.x] * sc;  o[5] = s_code[b.y] * sc;
            o[6] = s_code[b.z] * sc;  o[7] = s_code[b.w] * sc;
            stg_cs_v8(out + (size_t)(base + row) * 1024 + seg * 8, o);
        }
    }
}

extern "C" void kernel_launch(void* const* d_in, const int* in_sizes, int n_in,
                              void* d_out, int out_size) {
    const int*   x      = (const int*)d_in[0];
    const int*   q_idx  = (const int*)d_in[1];
    const float* absmax = (const float*)d_in[2];
    const float* code   = (const float*)d_in[3];
    float*       out    = (float*)d_out;

    const int n_tokens = in_sizes[0];   // 8*4096 = 32768
    const int grid = (n_tokens + TPC - 1) / TPC;
    bnb8bit_embedding_kernel<<<grid, 256>>>(x, q_idx, absmax, code, out, n_tokens);
}

// round 6
// speedup vs baseline: 1.0454x; 1.0454x over previous
#include <cuda_runtime.h>
#include <cuda_bf16.h>
#include <cstdint>

// BNB 8-bit embedding dequant-on-gather (sm_103a), R6.
// Identities: row base = q_idx + id*1024; scale = absmax[id>>2].
//
// Block = 128 threads, 4 tokens per CTA (grid 8192). Each thread owns one
// 32B segment of each of the 4 rows: 4 front-batched LDG.256 (MLP=4), then
// per-row dequant + STG.256 streaming store. Ids arrive as one broadcast
// int4 load; __syncthreads only protects the smem codebook.

#define TPC 4

__device__ __forceinline__ void ldg_nc_v8(const int* p, uint32_t r[8]) {
    asm volatile("ld.global.nc.v8.b32 {%0,%1,%2,%3,%4,%5,%6,%7}, [%8];"
                 : "=r"(r[0]), "=r"(r[1]), "=r"(r[2]), "=r"(r[3]),
                   "=r"(r[4]), "=r"(r[5]), "=r"(r[6]), "=r"(r[7])
                 : "l"(p));
}

__device__ __forceinline__ void stg_cs_v8(float* p, const float o[8]) {
    asm volatile("st.global.cs.v8.f32 [%0], {%1,%2,%3,%4,%5,%6,%7,%8};"
                 :: "l"(p),
                    "f"(o[0]), "f"(o[1]), "f"(o[2]), "f"(o[3]),
                    "f"(o[4]), "f"(o[5]), "f"(o[6]), "f"(o[7])
                 : "memory");
}

__global__ __launch_bounds__(128)
void bnb8bit_embedding_kernel(const int* __restrict__ x,
                              const int* __restrict__ q_idx,
                              const float* __restrict__ absmax,
                              const float* __restrict__ code,
                              float* __restrict__ out,
                              int n_tokens) {
    __shared__ float s_code[256];
    const int t = threadIdx.x;
    s_code[t]       = code[t];
    s_code[t + 128] = code[t + 128];

    const int base = blockIdx.x * TPC;

    if (base + TPC <= n_tokens) {
        // Fast path. x is int32; 4 consecutive ids = one aligned int4
        // (same address across the CTA -> broadcast, L1/L2 resident).
        const int4 ids = *reinterpret_cast<const int4*>(x + base);
        const int id0 = ids.x, id1 = ids.y, id2 = ids.z, id3 = ids.w;

        __syncthreads();   // codebook ready

        uint32_t v[TPC][8];
        float    sc[TPC];
        sc[0] = __ldg(absmax + (id0 >> 2));
        sc[1] = __ldg(absmax + (id1 >> 2));
        sc[2] = __ldg(absmax + (id2 >> 2));
        sc[3] = __ldg(absmax + (id3 >> 2));
        ldg_nc_v8(q_idx + (size_t)id0 * 1024 + t * 8, v[0]);
        ldg_nc_v8(q_idx + (size_t)id1 * 1024 + t * 8, v[1]);
        ldg_nc_v8(q_idx + (size_t)id2 * 1024 + t * 8, v[2]);
        ldg_nc_v8(q_idx + (size_t)id3 * 1024 + t * 8, v[3]);

        #pragma unroll
        for (int i = 0; i < TPC; i++) {
            float o[8];
            #pragma unroll
            for (int j = 0; j < 8; j++)
                o[j] = s_code[v[i][j]] * sc[i];
            stg_cs_v8(out + (size_t)(base + i) * 1024 + t * 8, o);
        }
    } else {
        __syncthreads();   // codebook ready
        for (int i = 0; i < TPC; i++) {
            const int tok = base + i;
            if (tok >= n_tokens) break;
            const int id = __ldg(x + tok);
            const float sc = __ldg(absmax + (id >> 2));
            uint32_t v[8];
            ldg_nc_v8(q_idx + (size_t)id * 1024 + t * 8, v);
            float o[8];
            #pragma unroll
            for (int j = 0; j < 8; j++)
                o[j] = s_code[v[j]] * sc;
            stg_cs_v8(out + (size_t)tok * 1024 + t * 8, o);
        }
    }
}

extern "C" void kernel_launch(void* const* d_in, const int* in_sizes, int n_in,
                              void* d_out, int out_size) {
    const int*   x      = (const int*)d_in[0];
    const int*   q_idx  = (const int*)d_in[1];
    const float* absmax = (const float*)d_in[2];
    const float* code   = (const float*)d_in[3];
    float*       out    = (float*)d_out;

    const int n_tokens = in_sizes[0];   // 8*4096 = 32768
    const int grid = (n_tokens + TPC - 1) / TPC;
    bnb8bit_embedding_kernel<<<grid, 128>>>(x, q_idx, absmax, code, out, n_tokens);
}